// round 5
// baseline (speedup 1.0000x reference)
#include <cuda_runtime.h>
#include <math.h>

#define BX 32
#define BY 8
#define TPT_X 4               // outputs per thread, x
#define TPT_Y 4               // outputs per thread, y
#define TILE_W (BX * TPT_X)   // 128
#define TILE_H (BY * TPT_Y)   // 32
#define SM_W (TILE_W + 4)     // 132
#define SM_H (TILE_H + 4)     // 36

// 2 blocks/SM -> reg ceiling 128: lets ptxas keep all 50 taps + 32 accumulators
// resident instead of rematerializing taps via LDG in the inner loop.
__global__ __launch_bounds__(BX * BY, 2)
void hitmiss_kernel(const float* __restrict__ in,
                    const float* __restrict__ Kh,
                    const float* __restrict__ Km,
                    float* __restrict__ out,
                    int H, int W, int Hout, int Wout)
{
    __shared__ __align__(16) float tile[SM_H][SM_W];

    const int tid  = threadIdx.y * BX + threadIdx.x;
    const int col0 = blockIdx.x * TILE_W;
    const int row0 = blockIdx.y * TILE_H;

    // --- cooperative tile load first (get DRAM loads in flight early) ---
    const int NW4 = SM_W / 4;          // 33
    const int NV  = NW4 * SM_H;        // 1188 float4 slots
    for (int idx = tid; idx < NV; idx += BX * BY) {
        int r  = idx / NW4;
        int c4 = idx - r * NW4;
        int gr = row0 + r; if (gr > H - 1) gr = H - 1;
        int gc = col0 + c4 * 4;
        float4 v;
        if (gc + 3 <= W - 1) {
            v = *reinterpret_cast<const float4*>(in + (size_t)gr * W + gc);
        } else {
            int c0 = gc     < W - 1 ? gc     : W - 1;
            int c1 = gc + 1 < W - 1 ? gc + 1 : W - 1;
            int c2 = gc + 2 < W - 1 ? gc + 2 : W - 1;
            int c3 = gc + 3 < W - 1 ? gc + 3 : W - 1;
            const float* rowp = in + (size_t)gr * W;
            v.x = rowp[c0]; v.y = rowp[c1]; v.z = rowp[c2]; v.w = rowp[c3];
        }
        *reinterpret_cast<float4*>(&tile[r][c4 * 4]) = v;
    }

    // --- all 50 taps into registers (warp-uniform broadcast, L1-resident) ---
    float kh[25], km[25];
#pragma unroll
    for (int i = 0; i < 25; ++i) {
        kh[i] = __ldg(Kh + i);
        km[i] = __ldg(Km + i);
    }

    __syncthreads();

    // --- 4x4 register-blocked hit-or-miss, row-streaming: each smem row read once ---
    const int lx = threadIdx.x * TPT_X;   // multiple of 4 -> aligned LDS.128
    const int ly = threadIdx.y * TPT_Y;

    float mn[TPT_Y * TPT_X], mx[TPT_Y * TPT_X];

#pragma unroll
    for (int r = 0; r < TPT_Y + 4; ++r) {          // 8 input rows
        float w[TPT_X + 4];
        float4 a = *reinterpret_cast<const float4*>(&tile[ly + r][lx]);
        float4 b = *reinterpret_cast<const float4*>(&tile[ly + r][lx + 4]);
        w[0] = a.x; w[1] = a.y; w[2] = a.z; w[3] = a.w;
        w[4] = b.x; w[5] = b.y; w[6] = b.z; w[7] = b.w;

#pragma unroll
        for (int orow = 0; orow < TPT_Y; ++orow) {
            const int di = r - orow;
            if (di < 0 || di > 4) continue;          // compile-time pruned
#pragma unroll
            for (int dj = 0; dj < 5; ++dj) {
                const float khv = kh[di * 5 + dj];
                const float kmv = km[di * 5 + dj];
#pragma unroll
                for (int oc = 0; oc < TPT_X; ++oc) {
                    const float v = w[oc + dj];
                    const int   o = orow * TPT_X + oc;
                    if (di == 0 && dj == 0) {        // first tap: plain assign
                        mn[o] = v - khv;
                        mx[o] = v - kmv;
                    } else {
                        mn[o] = fminf(mn[o], v - khv);   // FADD (fma) + FMNMX (alu)
                        mx[o] = fmaxf(mx[o], v - kmv);
                    }
                }
            }
        }
    }

    // --- stores: float4 fast path, scalar at right/bottom edges ---
    const int oc0 = col0 + lx;
    const int or0 = row0 + ly;
#pragma unroll
    for (int orow = 0; orow < TPT_Y; ++orow) {
        const int gro = or0 + orow;
        if (gro >= Hout) continue;
        float r0 = mn[orow * TPT_X + 0] - mx[orow * TPT_X + 0];
        float r1 = mn[orow * TPT_X + 1] - mx[orow * TPT_X + 1];
        float r2 = mn[orow * TPT_X + 2] - mx[orow * TPT_X + 2];
        float r3 = mn[orow * TPT_X + 3] - mx[orow * TPT_X + 3];
        float* orow_p = out + (size_t)gro * Wout;
        if (oc0 + 3 < Wout) {
            float4 o; o.x = r0; o.y = r1; o.z = r2; o.w = r3;
            *reinterpret_cast<float4*>(orow_p + oc0) = o;
        } else {
            if (oc0 + 0 < Wout) orow_p[oc0 + 0] = r0;
            if (oc0 + 1 < Wout) orow_p[oc0 + 1] = r1;
            if (oc0 + 2 < Wout) orow_p[oc0 + 2] = r2;
            if (oc0 + 3 < Wout) orow_p[oc0 + 3] = r3;
        }
    }
}

extern "C" void kernel_launch(void* const* d_in, const int* in_sizes, int n_in,
                              void* d_out, int out_size)
{
    const float* in = (const float*)d_in[0];
    const float* Kh = (const float*)d_in[1];
    const float* Km = (const float*)d_in[2];
    float* out = (float*)d_out;

    const int H = (int)lround(sqrt((double)in_sizes[0]));
    const int W = H;
    const int Hout = H - 4;
    const int Wout = W - 4;

    dim3 block(BX, BY);
    dim3 grid((Wout + TILE_W - 1) / TILE_W, (Hout + TILE_H - 1) / TILE_H);
    hitmiss_kernel<<<grid, block>>>(in, Kh, Km, out, H, W, Hout, Wout);
}

// round 6
// speedup vs baseline: 1.2353x; 1.2353x over previous
#include <cuda_runtime.h>
#include <math.h>

#define BX 32
#define BY 8
#define TPT_X 4               // outputs per thread, x
#define TPT_Y 2               // outputs per thread, y (reduced: fewer live regs)
#define TILE_W (BX * TPT_X)   // 128
#define TILE_H (BY * TPT_Y)   // 16
#define SM_W (TILE_W + 4)     // 132
#define SM_H (TILE_H + 4)     // 20

__global__ __launch_bounds__(BX * BY)
void hitmiss_kernel(const float* __restrict__ in,
                    const float* __restrict__ Kh,
                    const float* __restrict__ Km,
                    float* __restrict__ out,
                    int H, int W, int Hout, int Wout)
{
    __shared__ __align__(16) float tile[SM_H][SM_W];
    __shared__ float skh[25], skm[25];

    const int tid  = threadIdx.y * BX + threadIdx.x;
    const int col0 = blockIdx.x * TILE_W;
    const int row0 = blockIdx.y * TILE_H;

    // taps -> shared (LDS broadcast at use; zero GPR residency cost)
    if (tid < 25) {
        skh[tid] = Kh[tid];
        skm[tid] = Km[tid];
    }

    // --- cooperative tile load: 33 float4 per row x 20 rows ---
    const int NW4 = SM_W / 4;          // 33
    const int NV  = NW4 * SM_H;        // 660 float4 slots
    for (int idx = tid; idx < NV; idx += BX * BY) {
        int r  = idx / NW4;
        int c4 = idx - r * NW4;
        int gr = row0 + r; if (gr > H - 1) gr = H - 1;
        int gc = col0 + c4 * 4;
        float4 v;
        if (gc + 3 <= W - 1) {
            v = *reinterpret_cast<const float4*>(in + (size_t)gr * W + gc);
        } else {
            int c0 = gc     < W - 1 ? gc     : W - 1;
            int c1 = gc + 1 < W - 1 ? gc + 1 : W - 1;
            int c2 = gc + 2 < W - 1 ? gc + 2 : W - 1;
            int c3 = gc + 3 < W - 1 ? gc + 3 : W - 1;
            const float* rowp = in + (size_t)gr * W;
            v.x = rowp[c0]; v.y = rowp[c1]; v.z = rowp[c2]; v.w = rowp[c3];
        }
        *reinterpret_cast<float4*>(&tile[r][c4 * 4]) = v;
    }
    __syncthreads();

    // --- 4x2 register-blocked hit-or-miss, di-outer, tap loaded once per (di,dj) ---
    const int lx = threadIdx.x * TPT_X;   // multiple of 4 -> aligned LDS.128
    const int ly = threadIdx.y * TPT_Y;

    float mn[TPT_Y * TPT_X], mx[TPT_Y * TPT_X];

#pragma unroll
    for (int di = 0; di < 5; ++di) {
        // two window rows live at a time (16 regs)
        float w0[8], w1[8];
        {
            float4 a = *reinterpret_cast<const float4*>(&tile[ly + di][lx]);
            float4 b = *reinterpret_cast<const float4*>(&tile[ly + di][lx + 4]);
            w0[0]=a.x; w0[1]=a.y; w0[2]=a.z; w0[3]=a.w;
            w0[4]=b.x; w0[5]=b.y; w0[6]=b.z; w0[7]=b.w;
            float4 c = *reinterpret_cast<const float4*>(&tile[ly + di + 1][lx]);
            float4 d = *reinterpret_cast<const float4*>(&tile[ly + di + 1][lx + 4]);
            w1[0]=c.x; w1[1]=c.y; w1[2]=c.z; w1[3]=c.w;
            w1[4]=d.x; w1[5]=d.y; w1[6]=d.z; w1[7]=d.w;
        }
#pragma unroll
        for (int dj = 0; dj < 5; ++dj) {
            const float khv = skh[di * 5 + dj];   // one LDS broadcast each
            const float kmv = skm[di * 5 + dj];
#pragma unroll
            for (int oc = 0; oc < TPT_X; ++oc) {
                const float v0 = w0[oc + dj];
                const float v1 = w1[oc + dj];
                if (di == 0 && dj == 0) {          // first tap: plain assign
                    mn[oc]         = v0 - khv;
                    mx[oc]         = v0 - kmv;
                    mn[TPT_X + oc] = v1 - khv;
                    mx[TPT_X + oc] = v1 - kmv;
                } else {
                    mn[oc]         = fminf(mn[oc],         v0 - khv);
                    mx[oc]         = fmaxf(mx[oc],         v0 - kmv);
                    mn[TPT_X + oc] = fminf(mn[TPT_X + oc], v1 - khv);
                    mx[TPT_X + oc] = fmaxf(mx[TPT_X + oc], v1 - kmv);
                }
            }
        }
    }

    // --- stores: float4 fast path, scalar at right/bottom edges ---
    const int oc0 = col0 + lx;
    const int or0 = row0 + ly;
#pragma unroll
    for (int orow = 0; orow < TPT_Y; ++orow) {
        const int gro = or0 + orow;
        if (gro >= Hout) continue;
        float r0 = mn[orow * TPT_X + 0] - mx[orow * TPT_X + 0];
        float r1 = mn[orow * TPT_X + 1] - mx[orow * TPT_X + 1];
        float r2 = mn[orow * TPT_X + 2] - mx[orow * TPT_X + 2];
        float r3 = mn[orow * TPT_X + 3] - mx[orow * TPT_X + 3];
        float* orow_p = out + (size_t)gro * Wout;
        if (oc0 + 3 < Wout) {
            float4 o; o.x = r0; o.y = r1; o.z = r2; o.w = r3;
            *reinterpret_cast<float4*>(orow_p + oc0) = o;
        } else {
            if (oc0 + 0 < Wout) orow_p[oc0 + 0] = r0;
            if (oc0 + 1 < Wout) orow_p[oc0 + 1] = r1;
            if (oc0 + 2 < Wout) orow_p[oc0 + 2] = r2;
            if (oc0 + 3 < Wout) orow_p[oc0 + 3] = r3;
        }
    }
}

extern "C" void kernel_launch(void* const* d_in, const int* in_sizes, int n_in,
                              void* d_out, int out_size)
{
    const float* in = (const float*)d_in[0];
    const float* Kh = (const float*)d_in[1];
    const float* Km = (const float*)d_in[2];
    float* out = (float*)d_out;

    const int H = (int)lround(sqrt((double)in_sizes[0]));
    const int W = H;
    const int Hout = H - 4;
    const int Wout = W - 4;

    dim3 block(BX, BY);
    dim3 grid((Wout + TILE_W - 1) / TILE_W, (Hout + TILE_H - 1) / TILE_H);
    hitmiss_kernel<<<grid, block>>>(in, Kh, Km, out, H, W, Hout, Wout);
}

// round 7
// speedup vs baseline: 1.5128x; 1.2246x over previous
#include <cuda_runtime.h>
#include <math.h>

#define BX 32
#define BY 8
#define TPT_X 4               // outputs per thread, x
#define TPT_Y 4               // outputs per thread, y
#define TILE_W (BX * TPT_X)   // 128
#define TILE_H (BY * TPT_Y)   // 32
#define SM_W (TILE_W + 4)     // 132
#define SM_H (TILE_H + 4)     // 36

__global__ __launch_bounds__(BX * BY)
void hitmiss_kernel(const float* __restrict__ in,
                    const float* __restrict__ Kh,
                    const float* __restrict__ Km,
                    float* __restrict__ out,
                    int H, int W, int Hout, int Wout)
{
    __shared__ __align__(16) float tile[SM_H][SM_W];

    const int tid  = threadIdx.y * BX + threadIdx.x;
    const int col0 = blockIdx.x * TILE_W;
    const int row0 = blockIdx.y * TILE_H;

    // --- kernels into registers (warp-uniform broadcast loads) ---
    float kh[25], km[25];
#pragma unroll
    for (int i = 0; i < 25; ++i) {
        kh[i] = __ldg(Kh + i);
        km[i] = __ldg(Km + i);
    }

    // --- cooperative tile load: 33 float4 per row x 36 rows ---
    const int NW4 = SM_W / 4;          // 33
    const int NV  = NW4 * SM_H;        // 1188 float4 slots
    for (int idx = tid; idx < NV; idx += BX * BY) {
        int r  = idx / NW4;
        int c4 = idx - r * NW4;
        int gr = row0 + r; if (gr > H - 1) gr = H - 1;
        int gc = col0 + c4 * 4;
        float4 v;
        if (gc + 3 <= W - 1) {
            v = *reinterpret_cast<const float4*>(in + (size_t)gr * W + gc);
        } else {
            int c0 = gc     < W - 1 ? gc     : W - 1;
            int c1 = gc + 1 < W - 1 ? gc + 1 : W - 1;
            int c2 = gc + 2 < W - 1 ? gc + 2 : W - 1;
            int c3 = gc + 3 < W - 1 ? gc + 3 : W - 1;
            const float* rowp = in + (size_t)gr * W;
            v.x = rowp[c0]; v.y = rowp[c1]; v.z = rowp[c2]; v.w = rowp[c3];
        }
        *reinterpret_cast<float4*>(&tile[r][c4 * 4]) = v;
    }
    __syncthreads();

    // --- 4x4 register-blocked hit-or-miss, row-streaming.
    //     Per (output,row): 5 independent subs, then a BALANCED min tree
    //     written as fminf(fminf(a,b),c) so ptxas can fuse FMNMX3 (3-input
    //     min/max, Hopper+). Falls back to same-op-count FMNMX pairs. ---
    const int lx = threadIdx.x * TPT_X;   // multiple of 4 -> aligned LDS.128
    const int ly = threadIdx.y * TPT_Y;

    float mn[TPT_Y * TPT_X], mx[TPT_Y * TPT_X];

#pragma unroll
    for (int r = 0; r < TPT_Y + 4; ++r) {          // 8 input rows
        float w[TPT_X + 4];
        float4 a = *reinterpret_cast<const float4*>(&tile[ly + r][lx]);
        float4 b = *reinterpret_cast<const float4*>(&tile[ly + r][lx + 4]);
        w[0] = a.x; w[1] = a.y; w[2] = a.z; w[3] = a.w;
        w[4] = b.x; w[5] = b.y; w[6] = b.z; w[7] = b.w;

#pragma unroll
        for (int orow = 0; orow < TPT_Y; ++orow) {
            const int di = r - orow;
            if (di < 0 || di > 4) continue;          // compile-time pruned
#pragma unroll
            for (int oc = 0; oc < TPT_X; ++oc) {
                const int o = orow * TPT_X + oc;

                // 5 independent subtractions (fma pipe)
                float h0 = w[oc + 0] - kh[di * 5 + 0];
                float h1 = w[oc + 1] - kh[di * 5 + 1];
                float h2 = w[oc + 2] - kh[di * 5 + 2];
                float h3 = w[oc + 3] - kh[di * 5 + 3];
                float h4 = w[oc + 4] - kh[di * 5 + 4];
                float m0 = w[oc + 0] - km[di * 5 + 0];
                float m1 = w[oc + 1] - km[di * 5 + 1];
                float m2 = w[oc + 2] - km[di * 5 + 2];
                float m3 = w[oc + 3] - km[di * 5 + 3];
                float m4 = w[oc + 4] - km[di * 5 + 4];

                if (di == 0) {
                    // tournament of 5: two FMNMX3-shaped groups
                    mn[o] = fminf(fminf(fminf(h0, h1), h2), fminf(h3, h4));
                    mx[o] = fmaxf(fmaxf(fmaxf(m0, m1), m2), fmaxf(m3, m4));
                } else {
                    // tournament of 5 + accumulator: 2x (3-input) + 1 merge
                    float tA = fminf(fminf(h0, h1), h2);       // FMNMX3
                    float tB = fminf(fminf(h3, h4), mn[o]);    // FMNMX3
                    mn[o] = fminf(tA, tB);
                    float uA = fmaxf(fmaxf(m0, m1), m2);       // FMNMX3
                    float uB = fmaxf(fmaxf(m3, m4), mx[o]);    // FMNMX3
                    mx[o] = fmaxf(uA, uB);
                }
            }
        }
    }

    // --- stores: float4 fast path, scalar at right/bottom edges ---
    const int oc0 = col0 + lx;
    const int or0 = row0 + ly;
#pragma unroll
    for (int orow = 0; orow < TPT_Y; ++orow) {
        const int gro = or0 + orow;
        if (gro >= Hout) continue;
        float r0 = mn[orow * TPT_X + 0] - mx[orow * TPT_X + 0];
        float r1 = mn[orow * TPT_X + 1] - mx[orow * TPT_X + 1];
        float r2 = mn[orow * TPT_X + 2] - mx[orow * TPT_X + 2];
        float r3 = mn[orow * TPT_X + 3] - mx[orow * TPT_X + 3];
        float* orow_p = out + (size_t)gro * Wout;
        if (oc0 + 3 < Wout) {
            float4 o; o.x = r0; o.y = r1; o.z = r2; o.w = r3;
            *reinterpret_cast<float4*>(orow_p + oc0) = o;
        } else {
            if (oc0 + 0 < Wout) orow_p[oc0 + 0] = r0;
            if (oc0 + 1 < Wout) orow_p[oc0 + 1] = r1;
            if (oc0 + 2 < Wout) orow_p[oc0 + 2] = r2;
            if (oc0 + 3 < Wout) orow_p[oc0 + 3] = r3;
        }
    }
}

extern "C" void kernel_launch(void* const* d_in, const int* in_sizes, int n_in,
                              void* d_out, int out_size)
{
    const float* in = (const float*)d_in[0];
    const float* Kh = (const float*)d_in[1];
    const float* Km = (const float*)d_in[2];
    float* out = (float*)d_out;

    const int H = (int)lround(sqrt((double)in_sizes[0]));
    const int W = H;
    const int Hout = H - 4;
    const int Wout = W - 4;

    dim3 block(BX, BY);
    dim3 grid((Wout + TILE_W - 1) / TILE_W, (Hout + TILE_H - 1) / TILE_H);
    hitmiss_kernel<<<grid, block>>>(in, Kh, Km, out, H, W, Hout, Wout);
}

// round 8
// speedup vs baseline: 1.7339x; 1.1462x over previous
#include <cuda_runtime.h>
#include <math.h>

#define BX 32
#define BY 8
#define TPT_X 4               // outputs per thread, x
#define TPT_Y 4               // outputs per thread, y
#define TILE_W (BX * TPT_X)   // 128
#define TILE_H (BY * TPT_Y)   // 32
#define SM_W (TILE_W + 4)     // 132
#define SM_H (TILE_H + 4)     // 36

__global__ __launch_bounds__(BX * BY)
void hitmiss_kernel(const float* __restrict__ in,
                    const float* __restrict__ Kh,
                    const float* __restrict__ Km,
                    float* __restrict__ out,
                    int H, int W, int Hout, int Wout)
{
    __shared__ __align__(16) float tile[SM_H][SM_W];

    const int tid  = threadIdx.y * BX + threadIdx.x;
    const int col0 = blockIdx.x * TILE_W;
    const int row0 = blockIdx.y * TILE_H;

    // 96.8% of blocks: fully interior -> no divisions, no clamps, no predicates.
    const bool interior = (row0 + SM_H <= H) && (col0 + SM_W <= W);

    // --- kernels into registers (warp-uniform broadcast loads) ---
    float kh[25], km[25];
#pragma unroll
    for (int i = 0; i < 25; ++i) {
        kh[i] = __ldg(Kh + i);
        km[i] = __ldg(Km + i);
    }

    if (interior) {
        // --- fast loader: straight-line 2D indexing, all LDG.128 aligned ---
        const float* base = in + (size_t)row0 * W + col0;
        const int tx4 = threadIdx.x * 4;
#pragma unroll
        for (int i = 0; i < 4; ++i) {                 // rows 0..31
            const int r = threadIdx.y + 8 * i;
            *reinterpret_cast<float4*>(&tile[r][tx4]) =
                *reinterpret_cast<const float4*>(base + (size_t)r * W + tx4);
        }
        if (threadIdx.y < 4) {                        // rows 32..35
            const int r = 32 + threadIdx.y;
            *reinterpret_cast<float4*>(&tile[r][tx4]) =
                *reinterpret_cast<const float4*>(base + (size_t)r * W + tx4);
        }
        if (tid < SM_H) {                             // last float4 column (128..131)
            *reinterpret_cast<float4*>(&tile[tid][TILE_W]) =
                *reinterpret_cast<const float4*>(base + (size_t)tid * W + TILE_W);
        }
    } else {
        // --- boundary loader (rare): generic with clamps ---
        const int NW4 = SM_W / 4;          // 33
        const int NV  = NW4 * SM_H;        // 1188 float4 slots
        for (int idx = tid; idx < NV; idx += BX * BY) {
            int r  = idx / NW4;
            int c4 = idx - r * NW4;
            int gr = row0 + r; if (gr > H - 1) gr = H - 1;
            int gc = col0 + c4 * 4;
            float4 v;
            if (gc + 3 <= W - 1) {
                v = *reinterpret_cast<const float4*>(in + (size_t)gr * W + gc);
            } else {
                int c0 = gc     < W - 1 ? gc     : W - 1;
                int c1 = gc + 1 < W - 1 ? gc + 1 : W - 1;
                int c2 = gc + 2 < W - 1 ? gc + 2 : W - 1;
                int c3 = gc + 3 < W - 1 ? gc + 3 : W - 1;
                const float* rowp = in + (size_t)gr * W;
                v.x = rowp[c0]; v.y = rowp[c1]; v.z = rowp[c2]; v.w = rowp[c3];
            }
            *reinterpret_cast<float4*>(&tile[r][c4 * 4]) = v;
        }
    }
    __syncthreads();

    // --- 4x4 register-blocked hit-or-miss, row-streaming, FMNMX3 trees ---
    const int lx = threadIdx.x * TPT_X;   // multiple of 4 -> aligned LDS.128
    const int ly = threadIdx.y * TPT_Y;

    float mn[TPT_Y * TPT_X], mx[TPT_Y * TPT_X];

#pragma unroll
    for (int r = 0; r < TPT_Y + 4; ++r) {          // 8 input rows
        float w[TPT_X + 4];
        float4 a = *reinterpret_cast<const float4*>(&tile[ly + r][lx]);
        float4 b = *reinterpret_cast<const float4*>(&tile[ly + r][lx + 4]);
        w[0] = a.x; w[1] = a.y; w[2] = a.z; w[3] = a.w;
        w[4] = b.x; w[5] = b.y; w[6] = b.z; w[7] = b.w;

#pragma unroll
        for (int orow = 0; orow < TPT_Y; ++orow) {
            const int di = r - orow;
            if (di < 0 || di > 4) continue;          // compile-time pruned
#pragma unroll
            for (int oc = 0; oc < TPT_X; ++oc) {
                const int o = orow * TPT_X + oc;

                float h0 = w[oc + 0] - kh[di * 5 + 0];
                float h1 = w[oc + 1] - kh[di * 5 + 1];
                float h2 = w[oc + 2] - kh[di * 5 + 2];
                float h3 = w[oc + 3] - kh[di * 5 + 3];
                float h4 = w[oc + 4] - kh[di * 5 + 4];
                float m0 = w[oc + 0] - km[di * 5 + 0];
                float m1 = w[oc + 1] - km[di * 5 + 1];
                float m2 = w[oc + 2] - km[di * 5 + 2];
                float m3 = w[oc + 3] - km[di * 5 + 3];
                float m4 = w[oc + 4] - km[di * 5 + 4];

                if (di == 0) {
                    mn[o] = fminf(fminf(fminf(h0, h1), h2), fminf(h3, h4));
                    mx[o] = fmaxf(fmaxf(fmaxf(m0, m1), m2), fmaxf(m3, m4));
                } else {
                    float tA = fminf(fminf(h0, h1), h2);       // FMNMX3
                    float tB = fminf(fminf(h3, h4), mn[o]);    // FMNMX3
                    mn[o] = fminf(tA, tB);
                    float uA = fmaxf(fmaxf(m0, m1), m2);       // FMNMX3
                    float uB = fmaxf(fmaxf(m3, m4), mx[o]);    // FMNMX3
                    mx[o] = fmaxf(uA, uB);
                }
            }
        }
    }

    // --- stores ---
    const int oc0 = col0 + lx;
    const int or0 = row0 + ly;
    if (interior && (oc0 + 3 < Wout) && (or0 + TPT_Y <= Hout)) {
        float* p = out + (size_t)or0 * Wout + oc0;
#pragma unroll
        for (int orow = 0; orow < TPT_Y; ++orow) {
            float4 o;
            o.x = mn[orow * TPT_X + 0] - mx[orow * TPT_X + 0];
            o.y = mn[orow * TPT_X + 1] - mx[orow * TPT_X + 1];
            o.z = mn[orow * TPT_X + 2] - mx[orow * TPT_X + 2];
            o.w = mn[orow * TPT_X + 3] - mx[orow * TPT_X + 3];
            *reinterpret_cast<float4*>(p) = o;
            p += Wout;
        }
    } else {
#pragma unroll
        for (int orow = 0; orow < TPT_Y; ++orow) {
            const int gro = or0 + orow;
            if (gro >= Hout) continue;
            float r0 = mn[orow * TPT_X + 0] - mx[orow * TPT_X + 0];
            float r1 = mn[orow * TPT_X + 1] - mx[orow * TPT_X + 1];
            float r2 = mn[orow * TPT_X + 2] - mx[orow * TPT_X + 2];
            float r3 = mn[orow * TPT_X + 3] - mx[orow * TPT_X + 3];
            float* orow_p = out + (size_t)gro * Wout;
            if (oc0 + 0 < Wout) orow_p[oc0 + 0] = r0;
            if (oc0 + 1 < Wout) orow_p[oc0 + 1] = r1;
            if (oc0 + 2 < Wout) orow_p[oc0 + 2] = r2;
            if (oc0 + 3 < Wout) orow_p[oc0 + 3] = r3;
        }
    }
}

extern "C" void kernel_launch(void* const* d_in, const int* in_sizes, int n_in,
                              void* d_out, int out_size)
{
    const float* in = (const float*)d_in[0];
    const float* Kh = (const float*)d_in[1];
    const float* Km = (const float*)d_in[2];
    float* out = (float*)d_out;

    const int H = (int)lround(sqrt((double)in_sizes[0]));
    const int W = H;
    const int Hout = H - 4;
    const int Wout = W - 4;

    dim3 block(BX, BY);
    dim3 grid((Wout + TILE_W - 1) / TILE_W, (Hout + TILE_H - 1) / TILE_H);
    hitmiss_kernel<<<grid, block>>>(in, Kh, Km, out, H, W, Hout, Wout);
}